// round 14
// baseline (speedup 1.0000x reference)
#include <cuda_runtime.h>

// PositionwiseMaxPool2D: x [32,128,128,64] f32 NHWC -> out [32,64,64,64]
// For each 2x2 window, pick the position with max channel-sumsq, copy its
// 64-channel vector.
//
// R13: continue the winning geometry trend. Harness: block256=27.36,
// block512=27.10 (page-locality win). Try block=1024 (grid 2048): each CTA
// spans two contiguous 32KB input-row segments, further concentrating the
// per-channel DRAM address streams. Body/policy identical to R12:
// 16 lanes/pixel, __ldlu loads, __stcs store.

#define B_DIM 32
#define H_DIM 128
#define W_DIM 128
#define C_DIM 64
#define OH 64
#define OW 64
#define LANES_PER_PIX 16   // 64 channels / 4 per float4
#define C4 (C_DIM / 4)
#define BLOCK 1024

__global__ __launch_bounds__(BLOCK, 2)
void pos_maxpool2d_kernel(const float* __restrict__ x, float* __restrict__ out) {
    const int tid  = blockIdx.x * BLOCK + threadIdx.x;
    const int lane = tid & (LANES_PER_PIX - 1);
    const int op   = tid >> 4;                // output pixel index, < 32*64*64

    const int ow = op & (OW - 1);
    const int oh = (op >> 6) & (OH - 1);
    const int b  = op >> 12;

    const float4* __restrict__ xv = reinterpret_cast<const float4*>(x);

    const int base = ((b * H_DIM + 2 * oh) * W_DIM + 2 * ow) * C4;
    const int rs   = W_DIM * C4;

    const float4 v0 = __ldlu(xv + base + lane);            // (r=0,c=0)
    const float4 v1 = __ldlu(xv + base + C4 + lane);       // (r=0,c=1)
    const float4 v2 = __ldlu(xv + base + rs + lane);       // (r=1,c=0)
    const float4 v3 = __ldlu(xv + base + rs + C4 + lane);  // (r=1,c=1)

    float n0 = v0.x * v0.x + v0.y * v0.y + v0.z * v0.z + v0.w * v0.w;
    float n1 = v1.x * v1.x + v1.y * v1.y + v1.z * v1.z + v1.w * v1.w;
    float n2 = v2.x * v2.x + v2.y * v2.y + v2.z * v2.z + v2.w * v2.w;
    float n3 = v3.x * v3.x + v3.y * v3.y + v3.z * v3.z + v3.w * v3.w;

    // Butterfly reduction within each 16-lane group (subset of a warp).
    // All lanes end with bitwise-identical sums.
    #pragma unroll
    for (int s = LANES_PER_PIX / 2; s > 0; s >>= 1) {
        n0 += __shfl_xor_sync(0xffffffffu, n0, s);
        n1 += __shfl_xor_sync(0xffffffffu, n1, s);
        n2 += __shfl_xor_sync(0xffffffffu, n2, s);
        n3 += __shfl_xor_sync(0xffffffffu, n3, s);
    }

    // First-occurrence argmax (strict > matches jnp.argmax tie-break).
    int   idx  = 0;
    float best = n0;
    if (n1 > best) { best = n1; idx = 1; }
    if (n2 > best) { best = n2; idx = 2; }
    if (n3 > best) { best = n3; idx = 3; }

    float4 w = v0;
    if (idx == 1) w = v1;
    if (idx == 2) w = v2;
    if (idx == 3) w = v3;

    __stcs(reinterpret_cast<float4*>(out) + op * C4 + lane, w);
}

extern "C" void kernel_launch(void* const* d_in, const int* in_sizes, int n_in,
                              void* d_out, int out_size) {
    const float* x = (const float*)d_in[0];
    float* out = (float*)d_out;
    const int total_threads = B_DIM * OH * OW * LANES_PER_PIX; // 2,097,152
    const int grid = total_threads / BLOCK;                    // 2048
    pos_maxpool2d_kernel<<<grid, BLOCK>>>(x, out);
}

// round 15
// speedup vs baseline: 1.1892x; 1.1892x over previous
#include <cuda_runtime.h>

// PositionwiseMaxPool2D: x [32,128,128,64] f32 NHWC -> out [32,64,64,64]
// For each 2x2 window, pick the position with max channel-sumsq, copy its
// 64-channel vector.
//
// R14: confirmation re-bench of the measured-best configuration (R12).
// Search summary across 13 rounds:
//   cache policy : __ldlu loads best (27.36 @ b256); store hint irrelevant
//   geometry     : block 256=27.36, 512=27.10, 1024=27.36 -> 512 optimal
//   structure    : multi-pixel/persistent/MLP variants neutral or worse
//   L2 pinning   : rejected (-2us)
// Kernel sits at the HBM mixed-R/W ceiling (~6.1 TB/s, 160 MiB/launch
// mandatory traffic). This is R12 verbatim: block=512, grid=4096,
// 16 lanes/pixel, __ldlu loads, __stcs store.

#define B_DIM 32
#define H_DIM 128
#define W_DIM 128
#define C_DIM 64
#define OH 64
#define OW 64
#define LANES_PER_PIX 16   // 64 channels / 4 per float4
#define C4 (C_DIM / 4)
#define BLOCK 512

__global__ __launch_bounds__(BLOCK, 4)
void pos_maxpool2d_kernel(const float* __restrict__ x, float* __restrict__ out) {
    const int tid  = blockIdx.x * BLOCK + threadIdx.x;
    const int lane = tid & (LANES_PER_PIX - 1);
    const int op   = tid >> 4;                // output pixel index, < 32*64*64

    const int ow = op & (OW - 1);
    const int oh = (op >> 6) & (OH - 1);
    const int b  = op >> 12;

    const float4* __restrict__ xv = reinterpret_cast<const float4*>(x);

    const int base = ((b * H_DIM + 2 * oh) * W_DIM + 2 * ow) * C4;
    const int rs   = W_DIM * C4;

    const float4 v0 = __ldlu(xv + base + lane);            // (r=0,c=0)
    const float4 v1 = __ldlu(xv + base + C4 + lane);       // (r=0,c=1)
    const float4 v2 = __ldlu(xv + base + rs + lane);       // (r=1,c=0)
    const float4 v3 = __ldlu(xv + base + rs + C4 + lane);  // (r=1,c=1)

    float n0 = v0.x * v0.x + v0.y * v0.y + v0.z * v0.z + v0.w * v0.w;
    float n1 = v1.x * v1.x + v1.y * v1.y + v1.z * v1.z + v1.w * v1.w;
    float n2 = v2.x * v2.x + v2.y * v2.y + v2.z * v2.z + v2.w * v2.w;
    float n3 = v3.x * v3.x + v3.y * v3.y + v3.z * v3.z + v3.w * v3.w;

    // Butterfly reduction within each 16-lane group (subset of a warp).
    // All lanes end with bitwise-identical sums.
    #pragma unroll
    for (int s = LANES_PER_PIX / 2; s > 0; s >>= 1) {
        n0 += __shfl_xor_sync(0xffffffffu, n0, s);
        n1 += __shfl_xor_sync(0xffffffffu, n1, s);
        n2 += __shfl_xor_sync(0xffffffffu, n2, s);
        n3 += __shfl_xor_sync(0xffffffffu, n3, s);
    }

    // First-occurrence argmax (strict > matches jnp.argmax tie-break).
    int   idx  = 0;
    float best = n0;
    if (n1 > best) { best = n1; idx = 1; }
    if (n2 > best) { best = n2; idx = 2; }
    if (n3 > best) { best = n3; idx = 3; }

    float4 w = v0;
    if (idx == 1) w = v1;
    if (idx == 2) w = v2;
    if (idx == 3) w = v3;

    __stcs(reinterpret_cast<float4*>(out) + op * C4 + lane, w);
}

extern "C" void kernel_launch(void* const* d_in, const int* in_sizes, int n_in,
                              void* d_out, int out_size) {
    const float* x = (const float*)d_in[0];
    float* out = (float*)d_out;
    const int total_threads = B_DIM * OH * OW * LANES_PER_PIX; // 2,097,152
    const int grid = total_threads / BLOCK;                    // 4096
    pos_maxpool2d_kernel<<<grid, BLOCK>>>(x, out);
}